// round 2
// baseline (speedup 1.0000x reference)
#include <cuda_runtime.h>
#include <cuda_bf16.h>

// MultiGaussianReadoutLayer fused kernel, R2.
// B=32, O=12000 (H*N), F_IN=64, F_OUT=4, M=16.
//
// R2 changes vs R1 (L1 was 89.6% -> bound):
//  - x staged through smem with coalesced global loads; per-thread smem reads
//    use 68-float padded rows (17*16B) -> conflict-free 4-wavefront LDS.128.
//  - BG=2 batch rows per thread: each weight LDS.128 feeds 8 FMAs, halving
//    weight-LDS wavefronts per output pair.
// CTA: 8 instances x 32 batch rows, 128 threads (thread = (bgroup, o)).

#define B_    32
#define O_    12000
#define FIN   64
#define M_    16
#define OB    8
#define NT    128

#define SW_STRIDE 1028   // 64*16 + 4: o-stride mod 8 groups = 1 -> conflict-free
#define MW_STRIDE 260    // 64*4 + 4
#define X_STRIDE  68     // 64 + 4: 17*16B -> lane L hits group 17L mod 8

// smem layout (floats)
#define SW_OFF 0
#define MW_OFF (OB * SW_STRIDE)                 // 8224
#define SB_OFF (MW_OFF + OB * MW_STRIDE)        // 10304
#define MB_OFF (SB_OFF + OB * 16)               // 10432
#define SX_OFF (MB_OFF + OB * 4)                // 10464
#define SMEM_FLOATS (SX_OFF + B_ * OB * X_STRIDE)  // 27872 -> 111488 B

__global__ void __launch_bounds__(NT)
mgr_kernel(const float* __restrict__ x,
           const float* __restrict__ mu_w,
           const float* __restrict__ mu_b,
           const float* __restrict__ sigma_w,
           const float* __restrict__ sigma_b,
           const float* __restrict__ eps,
           float* __restrict__ out)
{
    extern __shared__ __align__(16) float smem[];
    float* sw = smem + SW_OFF;
    float* mw = smem + MW_OFF;
    float* sb = smem + SB_OFF;
    float* mb = smem + MB_OFF;
    float* sx = smem + SX_OFF;

    const int tid    = threadIdx.x;
    const int o_base = blockIdx.x * OB;

    // ---- stage sigma_w / mu_w / biases (coalesced float4) ----
    {
        const float4* src_s = (const float4*)(sigma_w + (size_t)o_base * 1024);
        #pragma unroll
        for (int i = tid; i < OB * 256; i += NT) {      // 2048 float4
            int o = i >> 8, r = i & 255;
            *(float4*)(sw + o * SW_STRIDE + r * 4) = src_s[i];
        }
        const float4* src_m = (const float4*)(mu_w + (size_t)o_base * 256);
        #pragma unroll
        for (int i = tid; i < OB * 64; i += NT) {       // 512 float4
            int o = i >> 6, r = i & 63;
            *(float4*)(mw + o * MW_STRIDE + r * 4) = src_m[i];
        }
        if (tid < OB * 16) sb[tid] = sigma_b[(size_t)o_base * 16 + tid];
        if (tid < OB * 4)  mb[tid] = mu_b[(size_t)o_base * 4 + tid];

        // ---- stage x tile: 32 b-chunks of (8 o x 64 f), coalesced ----
        #pragma unroll
        for (int i = tid; i < B_ * OB * 16; i += NT) {  // 4096 float4
            int b  = i >> 7;          // 128 float4 per b-chunk
            int r  = i & 127;
            int o  = r >> 4;
            int f4 = r & 15;
            float4 v = ((const float4*)x)[((size_t)b * O_ + o_base) * 16 + r];
            *(float4*)(sx + ((b * OB + o) * X_STRIDE) + f4 * 4) = v;
        }
    }
    __syncthreads();

    const int o_l = tid & (OB - 1);
    const int bg  = tid >> 3;            // 0..15
    const int b0  = bg;
    const int b1  = bg + 16;
    const int og  = o_base + o_l;

    const float* swp = sw + o_l * SW_STRIDE;
    const float* mwp = mw + o_l * MW_STRIDE;
    const float* xr0 = sx + (b0 * OB + o_l) * X_STRIDE;
    const float* xr1 = sx + (b1 * OB + o_l) * X_STRIDE;

    float sg0[16], sg1[16], m0[4], m1[4];
    #pragma unroll
    for (int k = 0; k < 16; k++) { sg0[k] = sb[o_l * 16 + k]; sg1[k] = sg0[k]; }
    #pragma unroll
    for (int l = 0; l < 4;  l++) { m0[l]  = mb[o_l * 4 + l];  m1[l]  = m0[l]; }

    // ---- mainloop: both matvecs, 2 batch rows per weight load ----
    #pragma unroll
    for (int f4 = 0; f4 < FIN / 4; f4++) {
        float4 xa = *(const float4*)(xr0 + f4 * 4);
        float4 xc = *(const float4*)(xr1 + f4 * 4);
        #pragma unroll
        for (int j = 0; j < 4; j++) {
            const int f = f4 * 4 + j;
            const float a = (j == 0) ? xa.x : (j == 1) ? xa.y : (j == 2) ? xa.z : xa.w;
            const float c = (j == 0) ? xc.x : (j == 1) ? xc.y : (j == 2) ? xc.z : xc.w;

            float4 mm = *(const float4*)(mwp + f * 4);
            m0[0] += a * mm.x; m0[1] += a * mm.y; m0[2] += a * mm.z; m0[3] += a * mm.w;
            m1[0] += c * mm.x; m1[1] += c * mm.y; m1[2] += c * mm.z; m1[3] += c * mm.w;

            #pragma unroll
            for (int k4 = 0; k4 < 4; k4++) {
                float4 ss = *(const float4*)(swp + f * 16 + k4 * 4);
                sg0[k4 * 4 + 0] += a * ss.x; sg0[k4 * 4 + 1] += a * ss.y;
                sg0[k4 * 4 + 2] += a * ss.z; sg0[k4 * 4 + 3] += a * ss.w;
                sg1[k4 * 4 + 0] += c * ss.x; sg1[k4 * 4 + 1] += c * ss.y;
                sg1[k4 * 4 + 2] += c * ss.z; sg1[k4 * 4 + 3] += c * ss.w;
            }
        }
    }

    // ---- eps application, 2 b rows x 16 samples, float4 coalesced ----
    const size_t beo0 = (size_t)b0 * O_ + og;
    const size_t beo1 = (size_t)b1 * O_ + og;
    #pragma unroll
    for (int m = 0; m < M_; m++) {
        {
            const size_t idx = ((size_t)m * B_ * O_ + beo0) * 4;
            float4 e = __ldg((const float4*)(eps + idx));
            float4 r;
            r.x = m0[0] + sg0[0]  * e.x + sg0[1]  * e.y + sg0[2]  * e.z + sg0[3]  * e.w;
            r.y = m0[1] + sg0[4]  * e.x + sg0[5]  * e.y + sg0[6]  * e.z + sg0[7]  * e.w;
            r.z = m0[2] + sg0[8]  * e.x + sg0[9]  * e.y + sg0[10] * e.z + sg0[11] * e.w;
            r.w = m0[3] + sg0[12] * e.x + sg0[13] * e.y + sg0[14] * e.z + sg0[15] * e.w;
            *(float4*)(out + idx) = r;
        }
        {
            const size_t idx = ((size_t)m * B_ * O_ + beo1) * 4;
            float4 e = __ldg((const float4*)(eps + idx));
            float4 r;
            r.x = m1[0] + sg1[0]  * e.x + sg1[1]  * e.y + sg1[2]  * e.z + sg1[3]  * e.w;
            r.y = m1[1] + sg1[4]  * e.x + sg1[5]  * e.y + sg1[6]  * e.z + sg1[7]  * e.w;
            r.z = m1[2] + sg1[8]  * e.x + sg1[9]  * e.y + sg1[10] * e.z + sg1[11] * e.w;
            r.w = m1[3] + sg1[12] * e.x + sg1[13] * e.y + sg1[14] * e.z + sg1[15] * e.w;
            *(float4*)(out + idx) = r;
        }
    }
}

extern "C" void kernel_launch(void* const* d_in, const int* in_sizes, int n_in,
                              void* d_out, int out_size)
{
    const float* x       = (const float*)d_in[0];
    const float* mu_w    = (const float*)d_in[1];
    const float* mu_b    = (const float*)d_in[2];
    const float* sigma_w = (const float*)d_in[3];
    const float* sigma_b = (const float*)d_in[4];
    const float* eps     = (const float*)d_in[5];
    float* out           = (float*)d_out;

    const int smem_bytes = SMEM_FLOATS * sizeof(float);   // 111488
    cudaFuncSetAttribute(mgr_kernel,
                         cudaFuncAttributeMaxDynamicSharedMemorySize, smem_bytes);

    dim3 grid(O_ / OB);   // 1500 CTAs
    dim3 block(NT);
    mgr_kernel<<<grid, block, smem_bytes>>>(x, mu_w, mu_b, sigma_w, sigma_b, eps, out);
}

// round 5
// speedup vs baseline: 1.2102x; 1.2102x over previous
#include <cuda_runtime.h>
#include <cuda_bf16.h>

// MultiGaussianReadoutLayer fused kernel, R3.
// B=32, O=12000 (H*N), F_IN=64, F_OUT=4, M=16.
//
// R3 = R1 shape (256 threads, thread=(b,o), 1 b-row per thread, 2 CTA/SM,
// 16 warps/SM) + R2's smem staging of x (kills the 8x L1 wavefront
// amplification of per-thread scattered row LDGs). Weights + x both in smem,
// conflict-free padded layouts.

#define B_    32
#define O_    12000
#define FIN   64
#define M_    16
#define OB    8
#define NT    256

#define SW_STRIDE 1028   // 64*16+4: o-stride mod 8 bank-groups = 1 -> bcast, conflict-free
#define MW_STRIDE 260    // 64*4+4
#define X_STRIDE  68     // 64+4: row r -> group r mod 8 -> clean 4-wavefront LDS.128

// smem layout (floats)
#define SW_OFF 0
#define MW_OFF (OB * SW_STRIDE)                    // 8224
#define SB_OFF (MW_OFF + OB * MW_STRIDE)           // 10304
#define MB_OFF (SB_OFF + OB * 16)                  // 10432
#define SX_OFF (MB_OFF + OB * 4)                   // 10464
#define SMEM_FLOATS (SX_OFF + B_ * OB * X_STRIDE)  // 27872 floats = 111488 B

__global__ void __launch_bounds__(NT, 2)
mgr_kernel(const float* __restrict__ x,
           const float* __restrict__ mu_w,
           const float* __restrict__ mu_b,
           const float* __restrict__ sigma_w,
           const float* __restrict__ sigma_b,
           const float* __restrict__ eps,
           float* __restrict__ out)
{
    extern __shared__ __align__(16) float smem[];
    float* sw = smem + SW_OFF;
    float* mw = smem + MW_OFF;
    float* sb = smem + SB_OFF;
    float* mb = smem + MB_OFF;
    float* sx = smem + SX_OFF;

    const int tid    = threadIdx.x;
    const int o_base = blockIdx.x * OB;

    // ---- stage weights + biases + x tile (all coalesced float4 LDG) ----
    {
        const float4* src_s = (const float4*)(sigma_w + (size_t)o_base * 1024);
        #pragma unroll
        for (int i = tid; i < OB * 256; i += NT) {      // 2048 float4
            int o = i >> 8, r = i & 255;
            *(float4*)(sw + o * SW_STRIDE + r * 4) = src_s[i];
        }
        const float4* src_m = (const float4*)(mu_w + (size_t)o_base * 256);
        #pragma unroll
        for (int i = tid; i < OB * 64; i += NT) {       // 512 float4
            int o = i >> 6, r = i & 63;
            *(float4*)(mw + o * MW_STRIDE + r * 4) = src_m[i];
        }
        if (tid < OB * 16) sb[tid] = sigma_b[(size_t)o_base * 16 + tid];
        if (tid < OB * 4)  mb[tid] = mu_b[(size_t)o_base * 4 + tid];

        // x tile: 32 b-chunks of (8 o x 64 f) = 64 KB, coalesced
        #pragma unroll
        for (int i = tid; i < B_ * OB * 16; i += NT) {  // 4096 float4
            int b  = i >> 7;           // 128 float4 per b-chunk
            int r  = i & 127;          // o*16 + f4
            int o  = r >> 4;
            int f4 = r & 15;
            float4 v = ((const float4*)x)[((size_t)b * O_ + o_base) * 16 + r];
            *(float4*)(sx + (b * OB + o) * X_STRIDE + f4 * 4) = v;
        }
    }
    __syncthreads();

    const int o_l = tid & (OB - 1);   // instance within block
    const int b   = tid >> 3;         // batch row 0..31
    const int og  = o_base + o_l;

    const float* swp = sw + o_l * SW_STRIDE;
    const float* mwp = mw + o_l * MW_STRIDE;
    const float* xr  = sx + (b * OB + o_l) * X_STRIDE;

    float sig[16], mu[4];
    #pragma unroll
    for (int k = 0; k < 16; k++) sig[k] = sb[o_l * 16 + k];
    #pragma unroll
    for (int l = 0; l < 4;  l++) mu[l]  = mb[o_l * 4 + l];

    // ---- mainloop: mu + sigma matvecs over F_IN=64 ----
    #pragma unroll
    for (int f4 = 0; f4 < FIN / 4; f4++) {
        float4 xv = *(const float4*)(xr + f4 * 4);
        #pragma unroll
        for (int j = 0; j < 4; j++) {
            const int f = f4 * 4 + j;
            const float xf = (j == 0) ? xv.x : (j == 1) ? xv.y : (j == 2) ? xv.z : xv.w;

            float4 m4 = *(const float4*)(mwp + f * 4);
            mu[0] += xf * m4.x; mu[1] += xf * m4.y;
            mu[2] += xf * m4.z; mu[3] += xf * m4.w;

            #pragma unroll
            for (int k4 = 0; k4 < 4; k4++) {
                float4 s4 = *(const float4*)(swp + f * 16 + k4 * 4);
                sig[k4 * 4 + 0] += xf * s4.x;
                sig[k4 * 4 + 1] += xf * s4.y;
                sig[k4 * 4 + 2] += xf * s4.z;
                sig[k4 * 4 + 3] += xf * s4.w;
            }
        }
    }

    // ---- eps application: [M, B, O, 4], per-warp float4 coalesced ----
    const size_t beo = (size_t)b * O_ + og;
    #pragma unroll
    for (int m = 0; m < M_; m++) {
        const size_t idx = ((size_t)m * B_ * O_ + beo) * 4;
        float4 e = __ldg((const float4*)(eps + idx));
        float4 r;
        r.x = mu[0] + sig[0]  * e.x + sig[1]  * e.y + sig[2]  * e.z + sig[3]  * e.w;
        r.y = mu[1] + sig[4]  * e.x + sig[5]  * e.y + sig[6]  * e.z + sig[7]  * e.w;
        r.z = mu[2] + sig[8]  * e.x + sig[9]  * e.y + sig[10] * e.z + sig[11] * e.w;
        r.w = mu[3] + sig[12] * e.x + sig[13] * e.y + sig[14] * e.z + sig[15] * e.w;
        *(float4*)(out + idx) = r;
    }
}

extern "C" void kernel_launch(void* const* d_in, const int* in_sizes, int n_in,
                              void* d_out, int out_size)
{
    const float* x       = (const float*)d_in[0];
    const float* mu_w    = (const float*)d_in[1];
    const float* mu_b    = (const float*)d_in[2];
    const float* sigma_w = (const float*)d_in[3];
    const float* sigma_b = (const float*)d_in[4];
    const float* eps     = (const float*)d_in[5];
    float* out           = (float*)d_out;

    const int smem_bytes = SMEM_FLOATS * sizeof(float);   // 111488
    cudaFuncSetAttribute(mgr_kernel,
                         cudaFuncAttributeMaxDynamicSharedMemorySize, smem_bytes);

    dim3 grid(O_ / OB);   // 1500 CTAs
    dim3 block(NT);
    mgr_kernel<<<grid, block, smem_bytes>>>(x, mu_w, mu_b, sigma_w, sigma_b, eps, out);
}

// round 6
// speedup vs baseline: 1.3844x; 1.1439x over previous
#include <cuda_runtime.h>
#include <cstdint>

// MultiGaussianReadoutLayer fused kernel, R6.
// B=32, O=12000, F_IN=64, F_OUT=4, M=16.
//
// R6: issue/latency was the binder (issue 22%, occ 23%, regs 126).
//  - fma.rn.f32x2 packed math: halves the FFMA instruction stream.
//  - x staged in f-quarters (5KB tile) -> smem 62KB/CTA -> 3 CTAs/SM.
//  - __launch_bounds__(256,3) forces regs <= 84 -> 24 warps/SM.

#define B_    32
#define O_    12000
#define FIN   64
#define M_    16
#define OB    8
#define NT    256
#define FQ    16            // f per staged quarter
#define NQ    (FIN / FQ)    // 4

#define SW_STRIDE 1028      // 64*16+4: o-lane bank-groups distinct -> conflict-free
#define MW_STRIDE 260       // 64*4+4
#define X_STRIDE  20        // FQ+4: odd 16B multiple -> clean 4-wf LDS.128

#define SW_OFF 0
#define MW_OFF (OB * SW_STRIDE)                    // 8224
#define SB_OFF (MW_OFF + OB * MW_STRIDE)           // 10304
#define MB_OFF (SB_OFF + OB * 16)                  // 10432
#define SX_OFF (MB_OFF + OB * 4)                   // 10464
#define SMEM_FLOATS (SX_OFF + B_ * OB * X_STRIDE)  // 15584 floats = 62336 B

__device__ __forceinline__ uint64_t pack2(float lo, float hi) {
    uint64_t r; asm("mov.b64 %0, {%1,%2};" : "=l"(r) : "f"(lo), "f"(hi)); return r;
}
__device__ __forceinline__ uint64_t ffma2(uint64_t a, uint64_t b, uint64_t c) {
    uint64_t d; asm("fma.rn.f32x2 %0, %1, %2, %3;" : "=l"(d) : "l"(a), "l"(b), "l"(c));
    return d;
}
__device__ __forceinline__ void unpack2(uint64_t v, float& lo, float& hi) {
    asm("mov.b64 {%0,%1}, %2;" : "=f"(lo), "=f"(hi) : "l"(v));
}

__global__ void __launch_bounds__(NT, 3)
mgr_kernel(const float* __restrict__ x,
           const float* __restrict__ mu_w,
           const float* __restrict__ mu_b,
           const float* __restrict__ sigma_w,
           const float* __restrict__ sigma_b,
           const float* __restrict__ eps,
           float* __restrict__ out)
{
    extern __shared__ __align__(16) float smem[];
    float* sw = smem + SW_OFF;
    float* mw = smem + MW_OFF;
    float* sb = smem + SB_OFF;
    float* mb = smem + MB_OFF;
    float* sx = smem + SX_OFF;

    const int tid    = threadIdx.x;
    const int o_base = blockIdx.x * OB;

    // ---- stage weights + biases (coalesced float4) ----
    {
        const float4* src_s = (const float4*)(sigma_w + (size_t)o_base * 1024);
        #pragma unroll
        for (int i = tid; i < OB * 256; i += NT) {
            int o = i >> 8, r = i & 255;
            *(float4*)(sw + o * SW_STRIDE + r * 4) = src_s[i];
        }
        const float4* src_m = (const float4*)(mu_w + (size_t)o_base * 256);
        #pragma unroll
        for (int i = tid; i < OB * 64; i += NT) {
            int o = i >> 6, r = i & 63;
            *(float4*)(mw + o * MW_STRIDE + r * 4) = src_m[i];
        }
        if (tid < OB * 16) sb[tid] = sigma_b[(size_t)o_base * 16 + tid];
        if (tid < OB * 4)  mb[tid] = mu_b[(size_t)o_base * 4 + tid];
    }

    const int o_l = tid & (OB - 1);
    const int b   = tid >> 3;          // 0..31
    const int og  = o_base + o_l;

    const float* swp = sw + o_l * SW_STRIDE;
    const float* mwp = mw + o_l * MW_STRIDE;
    const float* xr  = sx + (b * OB + o_l) * X_STRIDE;

    // packed accumulators: sacc[j] = (sig[2j], sig[2j+1]); macc[j] = (mu[2j], mu[2j+1])
    uint64_t sacc[8], macc[2];

    // ---- mainloop over 4 staged f-quarters ----
    #pragma unroll
    for (int q = 0; q < NQ; q++) {
        // stage x quarter: 1024 float4, 4 per thread, coalesced 64B segments
        #pragma unroll
        for (int i = tid; i < B_ * OB * (FQ / 4); i += NT) {
            int bb = i >> 5;
            int r  = i & 31;
            int o  = r >> 2;
            int f4 = r & 3;
            float4 v = ((const float4*)x)[((size_t)bb * O_ + o_base + o) * 16 + q * 4 + f4];
            *(float4*)(sx + (bb * OB + o) * X_STRIDE + f4 * 4) = v;
        }
        __syncthreads();

        if (q == 0) {   // init accumulators from biases (after first sync: sb/mb ready)
            #pragma unroll
            for (int j = 0; j < 8; j++) sacc[j] = pack2(sb[o_l * 16 + 2 * j], sb[o_l * 16 + 2 * j + 1]);
            macc[0] = pack2(mb[o_l * 4 + 0], mb[o_l * 4 + 1]);
            macc[1] = pack2(mb[o_l * 4 + 2], mb[o_l * 4 + 3]);
        }

        #pragma unroll
        for (int f4l = 0; f4l < FQ / 4; f4l++) {
            float4 xv = *(const float4*)(xr + f4l * 4);
            #pragma unroll
            for (int j = 0; j < 4; j++) {
                const int f = q * FQ + f4l * 4 + j;
                const float xf = (j == 0) ? xv.x : (j == 1) ? xv.y : (j == 2) ? xv.z : xv.w;
                const uint64_t xx = pack2(xf, xf);

                ulonglong2 m2 = *(const ulonglong2*)(mwp + f * 4);
                macc[0] = ffma2(m2.x, xx, macc[0]);
                macc[1] = ffma2(m2.y, xx, macc[1]);

                #pragma unroll
                for (int k4 = 0; k4 < 4; k4++) {
                    ulonglong2 s2 = *(const ulonglong2*)(swp + f * 16 + k4 * 4);
                    sacc[2 * k4 + 0] = ffma2(s2.x, xx, sacc[2 * k4 + 0]);
                    sacc[2 * k4 + 1] = ffma2(s2.y, xx, sacc[2 * k4 + 1]);
                }
            }
        }
        __syncthreads();
    }

    // ---- repack sigma by output-row pairs for the eps stage ----
    float sig[16], mu0, mu1, mu2, mu3;
    #pragma unroll
    for (int j = 0; j < 8; j++) unpack2(sacc[j], sig[2 * j], sig[2 * j + 1]);
    unpack2(macc[0], mu0, mu1);
    unpack2(macc[1], mu2, mu3);

    uint64_t ep01[4], ep23[4];
    #pragma unroll
    for (int f = 0; f < 4; f++) {
        ep01[f] = pack2(sig[f],     sig[4 + f]);    // rows (0,1)
        ep23[f] = pack2(sig[8 + f], sig[12 + f]);   // rows (2,3)
    }
    const uint64_t mu01 = pack2(mu0, mu1);
    const uint64_t mu23 = pack2(mu2, mu3);

    // ---- eps application: [M, B, O, 4] float4 coalesced ----
    const size_t beo = (size_t)b * O_ + og;
    #pragma unroll
    for (int m = 0; m < M_; m++) {
        const size_t idx = ((size_t)m * B_ * O_ + beo) * 4;
        float4 e = __ldg((const float4*)(eps + idx));
        uint64_t ex = pack2(e.x, e.x), ey = pack2(e.y, e.y);
        uint64_t ez = pack2(e.z, e.z), ew = pack2(e.w, e.w);

        uint64_t p01 = ffma2(ep01[0], ex, mu01);
        p01 = ffma2(ep01[1], ey, p01);
        p01 = ffma2(ep01[2], ez, p01);
        p01 = ffma2(ep01[3], ew, p01);

        uint64_t p23 = ffma2(ep23[0], ex, mu23);
        p23 = ffma2(ep23[1], ey, p23);
        p23 = ffma2(ep23[2], ez, p23);
        p23 = ffma2(ep23[3], ew, p23);

        float4 r;
        unpack2(p01, r.x, r.y);
        unpack2(p23, r.z, r.w);
        *(float4*)(out + idx) = r;
    }
}

extern "C" void kernel_launch(void* const* d_in, const int* in_sizes, int n_in,
                              void* d_out, int out_size)
{
    const float* x       = (const float*)d_in[0];
    const float* mu_w    = (const float*)d_in[1];
    const float* mu_b    = (const float*)d_in[2];
    const float* sigma_w = (const float*)d_in[3];
    const float* sigma_b = (const float*)d_in[4];
    const float* eps     = (const float*)d_in[5];
    float* out           = (float*)d_out;

    const int smem_bytes = SMEM_FLOATS * sizeof(float);   // 62336
    cudaFuncSetAttribute(mgr_kernel,
                         cudaFuncAttributeMaxDynamicSharedMemorySize, smem_bytes);

    dim3 grid(O_ / OB);   // 1500 CTAs
    dim3 block(NT);
    mgr_kernel<<<grid, block, smem_bytes>>>(x, mu_w, mu_b, sigma_w, sigma_b, eps, out);
}

// round 7
// speedup vs baseline: 1.7673x; 1.2766x over previous
#include <cuda_runtime.h>
#include <cstdint>

// MultiGaussianReadoutLayer fused kernel, R7.
// B=32, O=12000, F_IN=64, F_OUT=4, M=16.
//
// R7: LDS.128 costs 4 wavefronts (8 lanes/phase) and thread=(b,o) made every
// weight load move 512B through the crossbar. Remap mainloop to warp=o,
// lane=b so weight LDS.128 are full-warp broadcasts (1 wf, 128B unique).
// x staged transposed [f][b*9+o] (conflict-free LDS.32); sig/mu exchanged
// through smem to restore the (b,o) mapping for the coalesced eps stage.

#define B_    32
#define O_    12000
#define FIN   64
#define M_    16
#define OB    8
#define NT    256
#define FQ    16            // f per staged quarter
#define XSTR  289           // f-row stride: 289 % 32 == 1 (2-way STS, 0-conflict LDS)
#define EX_BS 164           // exchange b-stride (floats), 4-aligned, 164%32==4
#define EX_OS 20            // exchange o-stride (floats)

#define SW_OFF 0
#define MW_OFF (OB * 1024)                       // 8192
#define SB_OFF (MW_OFF + OB * 256)               // 10240
#define MB_OFF (SB_OFF + OB * 16)                // 10368
#define SX_OFF (MB_OFF + OB * 4)                 // 10400
#define SX_SIZE 5376                             // max(16*XSTR=4624, exchange 5244)
#define SMEM_FLOATS (SX_OFF + SX_SIZE)           // 15776 -> 63104 B

__device__ __forceinline__ uint64_t pack2(float lo, float hi) {
    uint64_t r; asm("mov.b64 %0, {%1,%2};" : "=l"(r) : "f"(lo), "f"(hi)); return r;
}
__device__ __forceinline__ uint64_t ffma2(uint64_t a, uint64_t b, uint64_t c) {
    uint64_t d; asm("fma.rn.f32x2 %0, %1, %2, %3;" : "=l"(d) : "l"(a), "l"(b), "l"(c));
    return d;
}
__device__ __forceinline__ void unpack2(uint64_t v, float& lo, float& hi) {
    asm("mov.b64 {%0,%1}, %2;" : "=f"(lo), "=f"(hi) : "l"(v));
}

__global__ void __launch_bounds__(NT, 3)
mgr_kernel(const float* __restrict__ x,
           const float* __restrict__ mu_w,
           const float* __restrict__ mu_b,
           const float* __restrict__ sigma_w,
           const float* __restrict__ sigma_b,
           const float* __restrict__ eps,
           float* __restrict__ out)
{
    extern __shared__ __align__(16) float smem[];
    float* sw = smem + SW_OFF;
    float* mw = smem + MW_OFF;
    float* sb = smem + SB_OFF;
    float* mb = smem + MB_OFF;
    float* sx = smem + SX_OFF;

    const int tid    = threadIdx.x;
    const int o_base = blockIdx.x * OB;

    // ---- stage weights + biases (coalesced float4, linear smem) ----
    {
        const float4* src_s = (const float4*)(sigma_w + (size_t)o_base * 1024);
        #pragma unroll
        for (int i = tid; i < OB * 256; i += NT)
            ((float4*)sw)[i] = src_s[i];
        const float4* src_m = (const float4*)(mu_w + (size_t)o_base * 256);
        #pragma unroll
        for (int i = tid; i < OB * 64; i += NT)
            ((float4*)mw)[i] = src_m[i];
        if (tid < OB * 16) sb[tid] = sigma_b[(size_t)o_base * 16 + tid];
        if (tid < OB * 4)  mb[tid] = mu_b[(size_t)o_base * 4 + tid];
    }

    // mainloop mapping: warp <-> instance, lane <-> batch row
    const int o_w  = tid >> 5;        // 0..7
    const int lane = tid & 31;        // b

    const float* swp = sw + o_w * 1024;
    const float* mwp = mw + o_w * 256;

    uint64_t sacc[8], macc[2];

    #pragma unroll
    for (int q = 0; q < 4; q++) {
        // ---- stage x quarter transposed: sx[f_local*XSTR + b*9 + o] ----
        #pragma unroll
        for (int i = tid; i < B_ * OB * (FQ / 4); i += NT) {   // 1024 float4
            int bb  = i >> 5;
            int r   = i & 31;
            int o   = r >> 2;
            int f4l = r & 3;
            float4 v = ((const float4*)x)[((size_t)bb * O_ + o_base + o) * 16 + q * 4 + f4l];
            float* dst = sx + (f4l * 4) * XSTR + bb * 9 + o;
            dst[0]        = v.x;
            dst[XSTR]     = v.y;
            dst[2 * XSTR] = v.z;
            dst[3 * XSTR] = v.w;
        }
        __syncthreads();

        if (q == 0) {  // biases visible after first sync
            #pragma unroll
            for (int j = 0; j < 8; j++)
                sacc[j] = pack2(sb[o_w * 16 + 2 * j], sb[o_w * 16 + 2 * j + 1]);
            macc[0] = pack2(mb[o_w * 4 + 0], mb[o_w * 4 + 1]);
            macc[1] = pack2(mb[o_w * 4 + 2], mb[o_w * 4 + 3]);
        }

        #pragma unroll
        for (int fl = 0; fl < FQ; fl++) {
            const int f = q * FQ + fl;
            const float xf = sx[fl * XSTR + lane * 9 + o_w];   // conflict-free LDS.32
            const uint64_t xx = pack2(xf, xf);

            // all weight loads below: warp-uniform address -> broadcast
            ulonglong2 m2 = *(const ulonglong2*)(mwp + f * 4);
            macc[0] = ffma2(m2.x, xx, macc[0]);
            macc[1] = ffma2(m2.y, xx, macc[1]);

            #pragma unroll
            for (int h = 0; h < 2; h++) {
                ulonglong2 sA = *(const ulonglong2*)(swp + f * 16 + h * 8);
                ulonglong2 sB = *(const ulonglong2*)(swp + f * 16 + h * 8 + 4);
                sacc[4 * h + 0] = ffma2(sA.x, xx, sacc[4 * h + 0]);
                sacc[4 * h + 1] = ffma2(sA.y, xx, sacc[4 * h + 1]);
                sacc[4 * h + 2] = ffma2(sB.x, xx, sacc[4 * h + 2]);
                sacc[4 * h + 3] = ffma2(sB.y, xx, sacc[4 * h + 3]);
            }
        }
        __syncthreads();
    }

    // ---- exchange sig/mu through smem: (o_w, lane=b) -> (b', o') ----
    {
        float* exw = sx + lane * EX_BS + o_w * EX_OS;
        *(ulonglong2*)(exw +  0) = make_ulonglong2(sacc[0], sacc[1]);
        *(ulonglong2*)(exw +  4) = make_ulonglong2(sacc[2], sacc[3]);
        *(ulonglong2*)(exw +  8) = make_ulonglong2(sacc[4], sacc[5]);
        *(ulonglong2*)(exw + 12) = make_ulonglong2(sacc[6], sacc[7]);
        *(ulonglong2*)(exw + 16) = make_ulonglong2(macc[0], macc[1]);
    }
    __syncthreads();

    const int o_l = tid & (OB - 1);
    const int b   = tid >> 3;
    const int og  = o_base + o_l;

    float sig[16], mu0, mu1, mu2, mu3;
    {
        const float* exr = sx + b * EX_BS + o_l * EX_OS;
        #pragma unroll
        for (int j = 0; j < 8; j++) {
            uint64_t v = ((const uint64_t*)exr)[j];
            unpack2(v, sig[2 * j], sig[2 * j + 1]);
        }
        uint64_t v0 = ((const uint64_t*)exr)[8];
        uint64_t v1 = ((const uint64_t*)exr)[9];
        unpack2(v0, mu0, mu1);
        unpack2(v1, mu2, mu3);
    }

    uint64_t ep01[4], ep23[4];
    #pragma unroll
    for (int f = 0; f < 4; f++) {
        ep01[f] = pack2(sig[f],     sig[4 + f]);
        ep23[f] = pack2(sig[8 + f], sig[12 + f]);
    }
    const uint64_t mu01 = pack2(mu0, mu1);
    const uint64_t mu23 = pack2(mu2, mu3);

    // ---- eps application: [M, B, O, 4] float4 coalesced ----
    const size_t beo = (size_t)b * O_ + og;
    #pragma unroll
    for (int m = 0; m < M_; m++) {
        const size_t idx = ((size_t)m * B_ * O_ + beo) * 4;
        float4 e = __ldg((const float4*)(eps + idx));
        uint64_t ex = pack2(e.x, e.x), ey = pack2(e.y, e.y);
        uint64_t ez = pack2(e.z, e.z), ew = pack2(e.w, e.w);

        uint64_t p01 = ffma2(ep01[0], ex, mu01);
        p01 = ffma2(ep01[1], ey, p01);
        p01 = ffma2(ep01[2], ez, p01);
        p01 = ffma2(ep01[3], ew, p01);

        uint64_t p23 = ffma2(ep23[0], ex, mu23);
        p23 = ffma2(ep23[1], ey, p23);
        p23 = ffma2(ep23[2], ez, p23);
        p23 = ffma2(ep23[3], ew, p23);

        float4 r;
        unpack2(p01, r.x, r.y);
        unpack2(p23, r.z, r.w);
        *(float4*)(out + idx) = r;
    }
}

extern "C" void kernel_launch(void* const* d_in, const int* in_sizes, int n_in,
                              void* d_out, int out_size)
{
    const float* x       = (const float*)d_in[0];
    const float* mu_w    = (const float*)d_in[1];
    const float* mu_b    = (const float*)d_in[2];
    const float* sigma_w = (const float*)d_in[3];
    const float* sigma_b = (const float*)d_in[4];
    const float* eps     = (const float*)d_in[5];
    float* out           = (float*)d_out;

    const int smem_bytes = SMEM_FLOATS * sizeof(float);   // 63104
    cudaFuncSetAttribute(mgr_kernel,
                         cudaFuncAttributeMaxDynamicSharedMemorySize, smem_bytes);

    dim3 grid(O_ / OB);   // 1500 CTAs
    dim3 block(NT);
    mgr_kernel<<<grid, block, smem_bytes>>>(x, mu_w, mu_b, sigma_w, sigma_b, eps, out);
}